// round 16
// baseline (speedup 1.0000x reference)
#include <cuda_runtime.h>
#include <cuda_bf16.h>
#include <cuda_fp16.h>
#include <cstdint>

// ---------------------------------------------------------------------------
// RelationNetwork v16  (= v15 + persistent work-stealing k13).
// k0  : fp32 -> bf16 hi/lo split of inputs; resets the k13 work counter.
// k13 : PERSISTENT uber-kernel, grid = 296 (one wave). Blocks [0,192) first
//       run their K1 mma GEMM tile, then ALL blocks steal K3a n-slices
//       (pos-proj stream -> pf fp16) from a global atomic counter.
// k234: fused aff+softmax+output GEMM, register-direct, pf fp16.
// ---------------------------------------------------------------------------

__device__ __half g_pfh[1024u * 16u * 1024u];            // 32 MB [n][g][m] fp16
__device__ __nv_bfloat16 g_hi [4096u * 1024u];           // input hi split
__device__ __nv_bfloat16 g_lo [4096u * 1024u];           // input lo split
__device__ __nv_bfloat16 g_qkh[2u * 16u * 1024u * 64u];  // Q,K hi [seg][g][n][64]
__device__ __nv_bfloat16 g_qkl[2u * 16u * 1024u * 64u];  // Q,K lo
__device__ __nv_bfloat16 g_ph [16u * 64u * 1024u];       // P^T hi [g][o][k]
__device__ __nv_bfloat16 g_pl [16u * 64u * 1024u];       // P^T lo
__device__ unsigned int g_ctr;                           // K3a slice counter

// ---- packed f32x2 helpers ---------------------------------------------------
__device__ __forceinline__ unsigned long long pack2(float a, float b) {
    unsigned long long r;
    asm("mov.b64 %0, {%1, %2};" : "=l"(r)
        : "r"(__float_as_uint(a)), "r"(__float_as_uint(b)));
    return r;
}
__device__ __forceinline__ void unpack2(unsigned long long v, float& a, float& b) {
    unsigned int lo, hi;
    asm("mov.b64 {%0, %1}, %2;" : "=r"(lo), "=r"(hi) : "l"(v));
    a = __uint_as_float(lo);
    b = __uint_as_float(hi);
}
__device__ __forceinline__ unsigned long long fma2(unsigned long long a,
                                                   unsigned long long b,
                                                   unsigned long long c) {
    unsigned long long d;
    asm("fma.rn.f32x2 %0, %1, %2, %3;" : "=l"(d) : "l"(a), "l"(b), "l"(c));
    return d;
}

// ---- mma.sync / cp.async helpers --------------------------------------------
__device__ __forceinline__ uint32_t smem_u32(const void* p) {
    uint32_t a;
    asm("{ .reg .u64 t; cvta.to.shared.u64 t, %1; cvt.u32.u64 %0, t; }"
        : "=r"(a) : "l"(p));
    return a;
}
#define CP16(s, g) \
    asm volatile("cp.async.cg.shared.global [%0], [%1], 16;" \
                 :: "r"(s), "l"(g) : "memory")
#define CP_COMMIT() asm volatile("cp.async.commit_group;" ::: "memory")
#define CP_WAIT(n)  asm volatile("cp.async.wait_group %0;" :: "n"(n) : "memory")
#define LDSM4(r, a) \
    asm volatile("ldmatrix.sync.aligned.m8n8.x4.shared.b16 {%0,%1,%2,%3}, [%4];" \
                 : "=r"((r)[0]), "=r"((r)[1]), "=r"((r)[2]), "=r"((r)[3]) \
                 : "r"(a))
#define MMA_BF16(d, a, b0, b1) \
    asm volatile("mma.sync.aligned.m16n8k16.row.col.f32.bf16.bf16.f32 " \
                 "{%0,%1,%2,%3}, {%4,%5,%6,%7}, {%8,%9}, {%0,%1,%2,%3};" \
                 : "+f"((d)[0]), "+f"((d)[1]), "+f"((d)[2]), "+f"((d)[3]) \
                 : "r"((a)[0]), "r"((a)[1]), "r"((a)[2]), "r"((a)[3]), \
                   "r"(b0), "r"(b1))

// pack two fp32 -> bf16x2 register (lo = a, hi = b)
__device__ __forceinline__ uint32_t bf2pack(float a, float b) {
    uint32_t r;
    asm("cvt.rn.bf16x2.f32 %0, %1, %2;" : "=r"(r) : "f"(b), "f"(a));
    return r;
}

// 64B-row swizzle: 4 chunks of 16B permuted by row pair.
__device__ __forceinline__ uint32_t swz(int r, int c) {
    return (uint32_t)(r * 64 + (((c ^ ((r >> 1) & 3)) & 3) << 4));
}
// 128B-row SW128 swizzle.
__device__ __forceinline__ uint32_t sw128(uint32_t off) {
    return off ^ ((off >> 3) & 0x70);
}

// ---------------------------------------------------------------------------
// k0: split inputs into bf16 hi + lo; block 0 resets the work counter.
// ---------------------------------------------------------------------------
__global__ __launch_bounds__(256) void k0_convert(
    const float* __restrict__ roi, const float* __restrict__ qw,
    const float* __restrict__ kw,  const float* __restrict__ ow)
{
    if (blockIdx.x == 0 && threadIdx.x == 0) g_ctr = 0;
    const size_t e = ((size_t)blockIdx.x * 256 + threadIdx.x) * 4;
    const float* src;
    size_t off;
    if (e < (1u << 20))      { src = roi; off = e; }
    else if (e < (2u << 20)) { src = qw;  off = e - (1u << 20); }
    else if (e < (3u << 20)) { src = kw;  off = e - (2u << 20); }
    else                     { src = ow;  off = e - (3u << 20); }
    const float4 v = *(const float4*)(src + off);
    float x[4] = {v.x, v.y, v.z, v.w};
    __nv_bfloat16 h[4], l[4];
#pragma unroll
    for (int i = 0; i < 4; i++) {
        h[i] = __float2bfloat16(x[i]);
        l[i] = __float2bfloat16(x[i] - __bfloat162float(h[i]));
    }
    ((__nv_bfloat162*)(g_hi + e))[0] = __nv_bfloat162(h[0], h[1]);
    ((__nv_bfloat162*)(g_hi + e))[1] = __nv_bfloat162(h[2], h[3]);
    ((__nv_bfloat162*)(g_lo + e))[0] = __nv_bfloat162(l[0], l[1]);
    ((__nv_bfloat162*)(g_lo + e))[1] = __nv_bfloat162(l[2], l[3]);
}

// ---------------------------------------------------------------------------
// K1 path pieces (used inside k13).
// ---------------------------------------------------------------------------
#define K1_STAGE 32768
#define K1_DSMEM 67584

__device__ __forceinline__ void k1_issue(uint32_t so, int row0, int col0,
                                         int kc, int tid)
{
#pragma unroll
    for (int j = 0; j < 2; j++) {
        const int id = tid + (j << 8);
        const int r = id >> 2, c = id & 3;
        const uint32_t s = so + swz(r, c);
        const size_t goA = (size_t)(row0 + r) * 1024 + (kc << 5) + (c << 3);
        const size_t goB = (size_t)(1024 + col0 + r) * 1024 + (kc << 5) + (c << 3);
        CP16(s,         g_hi + goA);
        CP16(s +  8192, g_lo + goA);
        CP16(s + 16384, g_hi + goB);
        CP16(s + 24576, g_lo + goB);
    }
    CP_COMMIT();
}

__device__ __forceinline__ void k1_compute(uint32_t so, float acc[4][4][4],
                                           int wm, int wn, int lane)
{
    const int arow = lane & 15;
    const int achk = lane >> 4;
#pragma unroll
    for (int ks = 0; ks < 2; ks++) {
        uint32_t ah[4][4], al[4][4], bh[2][4], bl[2][4];
#pragma unroll
        for (int mi = 0; mi < 4; mi++) {
            const int r = wm * 64 + mi * 16 + arow;
            const uint32_t addr = so + swz(r, ks * 2 + achk);
            LDSM4(ah[mi], addr);
            LDSM4(al[mi], addr + 8192);
        }
#pragma unroll
        for (int nj = 0; nj < 2; nj++) {
            const int r = wn * 32 + nj * 16 + arow;
            const uint32_t addr = so + 16384 + swz(r, ks * 2 + achk);
            LDSM4(bh[nj], addr);
            LDSM4(bl[nj], addr + 8192);
        }
#pragma unroll
        for (int mi = 0; mi < 4; mi++)
#pragma unroll
            for (int n = 0; n < 4; n++) {
                const int nj = n >> 1, sb = n & 1;
                MMA_BF16(acc[mi][n], ah[mi], bh[nj][sb], bh[nj][sb + 2]);
                MMA_BF16(acc[mi][n], ah[mi], bl[nj][sb], bl[nj][sb + 2]);
                MMA_BF16(acc[mi][n], al[mi], bh[nj][sb], bh[nj][sb + 2]);
            }
    }
}

// ---------------------------------------------------------------------------
// k13: persistent uber-kernel, grid 296. bid<192: K1 tile first.
// Then ALL blocks steal K3a n-slices from g_ctr until exhausted.
// ---------------------------------------------------------------------------
__global__ __launch_bounds__(256, 2) void k13(
    const float* __restrict__ qb, const float* __restrict__ kb,
    const float* __restrict__ pe, const float* __restrict__ pw,
    const float* __restrict__ pb)
{
    extern __shared__ char sm1[];
    __shared__ ulonglong2 swd2[16][32];
    __shared__ float sb3[16];
    __shared__ int s_n;
    const int tid = threadIdx.x;

    if (blockIdx.x < 192) {
        // =========================== K1 phase ================================
        __shared__ float sbias[128];
        const uint32_t sbase = smem_u32(sm1);
        const int lane = tid & 31, wid = tid >> 5;
        const int wm = wid >> 2, wn = wid & 3;
        const int col0 = ((int)blockIdx.x % 24) << 7;
        const int row0 = ((int)blockIdx.x / 24) << 7;
        const int seg = col0 >> 10, jb0 = col0 & 1023;

        if (tid < 128)
            sbias[tid] = (seg == 0) ? qb[jb0 + tid]
                       : ((seg == 1) ? kb[jb0 + tid] : 0.0f);

        float acc[4][4][4];
#pragma unroll
        for (int i = 0; i < 4; i++)
#pragma unroll
            for (int j = 0; j < 4; j++)
#pragma unroll
                for (int q = 0; q < 4; q++) acc[i][j][q] = 0.0f;

        k1_issue(sbase, row0, col0, 0, tid);

#pragma unroll 1
        for (int kc = 0; kc < 32; kc++) {
            const uint32_t so = sbase + ((kc & 1) ? (uint32_t)K1_STAGE : 0u);
            if (kc < 31) {
                k1_issue(sbase + (((kc + 1) & 1) ? (uint32_t)K1_STAGE : 0u),
                         row0, col0, kc + 1, tid);
                CP_WAIT(1);
            } else {
                CP_WAIT(0);
            }
            __syncthreads();
            k1_compute(so, acc, wm, wn, lane);
            __syncthreads();
        }

        if (seg < 2) {
#pragma unroll
            for (int mi = 0; mi < 4; mi++) {
                const int r0 = row0 + wm * 64 + mi * 16 + (lane >> 2);
#pragma unroll
                for (int n = 0; n < 4; n++) {
                    const int lc = wn * 32 + n * 8 + ((lane & 3) << 1);
                    const int jl = jb0 + lc;
                    const int g = jl >> 6, d0 = jl & 63;
                    const float b0 = sbias[lc], b1 = sbias[lc + 1];
                    const float f00 = acc[mi][n][0] + b0;
                    const float f01 = acc[mi][n][1] + b1;
                    const float f10 = acc[mi][n][2] + b0;
                    const float f11 = acc[mi][n][3] + b1;
                    const size_t bi = ((size_t)(seg * 16 + g) * 1024) * 64 + d0;
                    __nv_bfloat16 h00 = __float2bfloat16(f00);
                    __nv_bfloat16 h01 = __float2bfloat16(f01);
                    __nv_bfloat16 h10 = __float2bfloat16(f10);
                    __nv_bfloat16 h11 = __float2bfloat16(f11);
                    *(__nv_bfloat162*)(g_qkh + bi + (size_t)r0 * 64) =
                        __nv_bfloat162(h00, h01);
                    *(__nv_bfloat162*)(g_qkh + bi + (size_t)(r0 + 8) * 64) =
                        __nv_bfloat162(h10, h11);
                    *(__nv_bfloat162*)(g_qkl + bi + (size_t)r0 * 64) =
                        __nv_bfloat162(
                            __float2bfloat16(f00 - __bfloat162float(h00)),
                            __float2bfloat16(f01 - __bfloat162float(h01)));
                    *(__nv_bfloat162*)(g_qkl + bi + (size_t)(r0 + 8) * 64) =
                        __nv_bfloat162(
                            __float2bfloat16(f10 - __bfloat162float(h10)),
                            __float2bfloat16(f11 - __bfloat162float(h11)));
                }
            }
        } else {
            // transpose through smem: smf[col][row] stride 132
            float* smf = (float*)sm1;
#pragma unroll
            for (int mi = 0; mi < 4; mi++) {
                const int rl = wm * 64 + mi * 16 + (lane >> 2);
#pragma unroll
                for (int n = 0; n < 4; n++) {
                    const int lc = wn * 32 + n * 8 + ((lane & 3) << 1);
                    smf[lc * 132 + rl]           = acc[mi][n][0];
                    smf[(lc + 1) * 132 + rl]     = acc[mi][n][1];
                    smf[lc * 132 + rl + 8]       = acc[mi][n][2];
                    smf[(lc + 1) * 132 + rl + 8] = acc[mi][n][3];
                }
            }
            __syncthreads();
            const int c = tid >> 1, half = tid & 1;
            const int jl = jb0 + c;
            const int g = jl >> 6, o = jl & 63;
            __nv_bfloat16* dh = g_ph + ((size_t)g * 64 + o) * 1024 +
                                row0 + half * 64;
            __nv_bfloat16* dl = g_pl + ((size_t)g * 64 + o) * 1024 +
                                row0 + half * 64;
            const float* srow = smf + c * 132 + half * 64;
#pragma unroll
            for (int i4 = 0; i4 < 16; i4++) {
                const float4 v = *(const float4*)(srow + i4 * 4);
                __nv_bfloat16 h0 = __float2bfloat16(v.x);
                __nv_bfloat16 h1 = __float2bfloat16(v.y);
                __nv_bfloat16 h2 = __float2bfloat16(v.z);
                __nv_bfloat16 h3 = __float2bfloat16(v.w);
                ((__nv_bfloat162*)(dh + i4 * 4))[0] = __nv_bfloat162(h0, h1);
                ((__nv_bfloat162*)(dh + i4 * 4))[1] = __nv_bfloat162(h2, h3);
                ((__nv_bfloat162*)(dl + i4 * 4))[0] = __nv_bfloat162(
                    __float2bfloat16(v.x - __bfloat162float(h0)),
                    __float2bfloat16(v.y - __bfloat162float(h1)));
                ((__nv_bfloat162*)(dl + i4 * 4))[1] = __nv_bfloat162(
                    __float2bfloat16(v.z - __bfloat162float(h2)),
                    __float2bfloat16(v.w - __bfloat162float(h3)));
            }
            __syncthreads();
        }
    }

    // ======================= K3a stealing phase ==============================
    for (int idx = tid; idx < 1024; idx += 256) {
        const float w = pw[idx];
        ((unsigned long long*)swd2)[idx] = pack2(w, w);
    }
    if (tid < 16) sb3[tid] = pb[tid];
    __syncthreads();

    const int m0 = tid << 2;
    while (true) {
        if (tid == 0) s_n = (int)atomicAdd(&g_ctr, 1u);
        __syncthreads();
        const int n = s_n;
        if (n >= 1024) break;

        unsigned long long acc[16][2];
#pragma unroll
        for (int gg = 0; gg < 16; gg++) { acc[gg][0] = 0ULL; acc[gg][1] = 0ULL; }

        const float* base = pe + (size_t)n * 1024 + m0;
        ulonglong2 cur[8];
#pragma unroll
        for (int j = 0; j < 8; j++)
            cur[j] = __ldg((const ulonglong2*)(base + (size_t)j * 1048576));

#pragma unroll 1
        for (int e0 = 0; e0 < 64; e0 += 8) {
            ulonglong2 nxt[8];
            const int eb = (e0 + 8) & 63;
#pragma unroll
            for (int j = 0; j < 8; j++)
                nxt[j] = __ldg((const ulonglong2*)
                               (base + (size_t)(eb + j) * 1048576));
#pragma unroll
            for (int j = 0; j < 8; j += 2) {
                const ulonglong2 c0 = cur[j], c1 = cur[j + 1];
                const int ep = (e0 + j) >> 1;
#pragma unroll
                for (int gg = 0; gg < 16; gg++) {
                    const ulonglong2 w = swd2[gg][ep];
                    acc[gg][0] = fma2(w.x, c0.x, acc[gg][0]);
                    acc[gg][0] = fma2(w.y, c1.x, acc[gg][0]);
                    acc[gg][1] = fma2(w.x, c0.y, acc[gg][1]);
                    acc[gg][1] = fma2(w.y, c1.y, acc[gg][1]);
                }
            }
#pragma unroll
            for (int j = 0; j < 8; j++) cur[j] = nxt[j];
        }

        __half* pfp = g_pfh + (size_t)n * 16 * 1024 + m0;
#pragma unroll
        for (int gg = 0; gg < 16; gg++) {
            float x0, x1, x2, x3;
            unpack2(acc[gg][0], x0, x1);
            unpack2(acc[gg][1], x2, x3);
            const float bgg = sb3[gg];
            __half2 ha = __floats2half2_rn(fmaxf(x0 + bgg, 1e-6f),
                                           fmaxf(x1 + bgg, 1e-6f));
            __half2 hb = __floats2half2_rn(fmaxf(x2 + bgg, 1e-6f),
                                           fmaxf(x3 + bgg, 1e-6f));
            uint2 v;
            v.x = *reinterpret_cast<uint32_t*>(&ha);
            v.y = *reinterpret_cast<uint32_t*>(&hb);
            *(uint2*)(pfp + (size_t)gg * 1024) = v;
        }
        __syncthreads();   // all s_n reads done before next overwrite
    }
}

// ---------------------------------------------------------------------------
// k234: fused aff + softmax + output GEMM, register-direct, pf fp16.
// Block = (g, 64n), 128 threads (4 warps x 16n x 64m / 64o).
// ---------------------------------------------------------------------------
#define K234_ST0   16384
#define K234_STAGE 25600
#define K234_LWOFF 16384
#define K234_POFF  (K234_ST0 + 2 * K234_STAGE)      // 67584
#define K234_DSMEM (K234_POFF + 16384)              // 83968

__device__ __forceinline__ void k234_issueS(uint32_t so, int g, int n0,
                                            int m0, int tid)
{
#pragma unroll
    for (int j = 0; j < 4; j++) {
        const int id = tid + (j << 7);
        const int r = id >> 3, c = id & 7;
        const size_t go = ((size_t)((16 + g) * 1024) + m0 + r) * 64 + (c << 3);
        const uint32_t s = so + sw128((r << 7) + (c << 4));
        CP16(s,        g_qkh + go);
        CP16(s + 8192, g_qkl + go);
    }
#pragma unroll
    for (int j = 0; j < 4; j++) {
        const int id = tid + (j << 7);
        const int r = id >> 3, c = id & 7;
        CP16(so + K234_LWOFF + r * 144 + (c << 4),
             g_pfh + ((size_t)(n0 + r) * 16 + g) * 1024 + m0 + (c << 3));
    }
    CP_COMMIT();
}

__device__ __forceinline__ void k234_issueP(uint32_t sp, int g, int m0, int tid)
{
#pragma unroll
    for (int j = 0; j < 4; j++) {
        const int id = tid + (j << 7);
        const int r = id >> 3, c = id & 7;
        const size_t gb = ((size_t)g * 64 + r) * 1024 + m0 + (c << 3);
        const uint32_t s = sp + sw128((r << 7) + (c << 4));
        CP16(s,        g_ph + gb);
        CP16(s + 8192, g_pl + gb);
    }
    CP_COMMIT();
}

__global__ __launch_bounds__(128, 2) void k234(float* __restrict__ out,
                                               const float* __restrict__ obias)
{
    extern __shared__ char smx[];
    __shared__ float srow[64];
    __shared__ float sbias[64];
    const uint32_t sbase = smem_u32(smx);
    const int tid = threadIdx.x, lane = tid & 31, w = tid >> 5;
    const int n0 = blockIdx.x << 6, g = blockIdx.y;

    if (tid < 64) {
        srow[tid] = 0.0f;
        sbias[tid] = obias[(g << 6) + tid];
    }

#pragma unroll
    for (int j = 0; j < 4; j++) {
        const int id = tid + (j << 7);
        const int r = id >> 3, c = id & 7;
        const size_t go = ((size_t)(g * 1024) + n0 + r) * 64 + (c << 3);
        const uint32_t s = sbase + sw128((r << 7) + (c << 4));
        CP16(s,        g_qkh + go);
        CP16(s + 8192, g_qkl + go);
    }
    k234_issueS(sbase + K234_ST0, g, n0, 0, tid);
    k234_issueP(sbase + K234_POFF, g, 0, tid);

    const int arow = lane & 15, achk = lane >> 4;
    const int r = lane >> 2, c2 = (lane & 3) << 1;
    const int grow = w * 16 + r;

    float acc2[8][4];
#pragma unroll
    for (int t = 0; t < 8; t++)
#pragma unroll
        for (int q = 0; q < 4; q++) acc2[t][q] = 0.0f;
    float rs0 = 0.0f, rs1 = 0.0f;

#pragma unroll 1
    for (int kc = 0; kc < 16; kc++) {
        const uint32_t so = sbase + K234_ST0 + (kc & 1) * (uint32_t)K234_STAGE;
        const char* lwb = smx + (so - sbase) + K234_LWOFF;
        if (kc < 15) {
            k234_issueS(sbase + K234_ST0 + ((kc + 1) & 1) * (uint32_t)K234_STAGE,
                        g, n0, (kc + 1) << 6, tid);
            CP_WAIT(1);
        } else {
            CP_WAIT(0);
        }
        __syncthreads();

        float acc1[8][4];
#pragma unroll
        for (int t = 0; t < 8; t++)
#pragma unroll
            for (int q = 0; q < 4; q++) acc1[t][q] = 0.0f;

#pragma unroll
        for (int ks = 0; ks < 4; ks++) {
            uint32_t ah4[4], al4[4];
            {
                const uint32_t addr = sbase +
                    sw128(((w * 16 + arow) << 7) + (ks << 5) + (achk << 4));
                LDSM4(ah4, addr);
                LDSM4(al4, addr + 8192);
            }
#pragma unroll
            for (int t = 0; t < 4; t++) {
                uint32_t bh[4], bl[4];
                const uint32_t addr = so +
                    sw128(((t * 16 + arow) << 7) + (ks << 5) + (achk << 4));
                LDSM4(bh, addr);
                LDSM4(bl, addr + 8192);
#pragma unroll
                for (int s = 0; s < 2; s++) {
                    const int nj = 2 * t + s;
                    MMA_BF16(acc1[nj], ah4, bh[s], bh[s + 2]);
                    MMA_BF16(acc1[nj], ah4, bl[s], bl[s + 2]);
                    MMA_BF16(acc1[nj], al4, bh[s], bh[s + 2]);
                }
            }
        }

#pragma unroll
        for (int t = 0; t < 8; t++) {
            const int mc = 8 * t + c2;
            const __half2 p0 =
                *(const __half2*)(lwb + grow * 144 + (mc << 1));
            const __half2 p1 =
                *(const __half2*)(lwb + (grow + 8) * 144 + (mc << 1));
            const float2 f0 = __half22float2(p0);
            const float2 f1 = __half22float2(p1);
            const float e0 = f0.x * __expf(0.125f * acc1[t][0]);
            const float e1 = f0.y * __expf(0.125f * acc1[t][1]);
            const float e2 = f1.x * __expf(0.125f * acc1[t][2]);
            const float e3 = f1.y * __expf(0.125f * acc1[t][3]);
            rs0 += e0 + e1;
            rs1 += e2 + e3;
            acc1[t][0] = e0; acc1[t][1] = e1;
            acc1[t][2] = e2; acc1[t][3] = e3;
        }

        uint32_t eh[4][4], el[4][4];
#pragma unroll
        for (int j = 0; j < 4; j++) {
#pragma unroll
            for (int h = 0; h < 4; h++) {
                const int t = 2 * j + (h >> 1);
                const float x = acc1[t][(h & 1) * 2];
                const float y = acc1[t][(h & 1) * 2 + 1];
                const uint32_t hp = bf2pack(x, y);
                eh[j][h] = hp;
                const __nv_bfloat162 hv = *(const __nv_bfloat162*)&hp;
                el[j][h] = bf2pack(x - __bfloat162float(hv.x),
                                   y - __bfloat162float(hv.y));
            }
        }

        const uint32_t pa = sbase + K234_POFF;
#pragma unroll
        for (int ks = 0; ks < 4; ks++) {
#pragma unroll
            for (int t = 0; t < 4; t++) {
                uint32_t bh[4], bl[4];
                const uint32_t addr = pa +
                    sw128(((t * 16 + arow) << 7) + (ks << 5) + (achk << 4));
                LDSM4(bh, addr);
                LDSM4(bl, addr + 8192);
#pragma unroll
                for (int s = 0; s < 2; s++) {
                    const int nj = 2 * t + s;
                    MMA_BF16(acc2[nj], eh[ks], bh[s], bh[s + 2]);
                    MMA_BF16(acc2[nj], eh[ks], bl[s], bl[s + 2]);
                    MMA_BF16(acc2[nj], el[ks], bh[s], bh[s + 2]);
                }
            }
        }
        __syncthreads();

        if (kc < 15)
            k234_issueP(pa, g, (kc + 1) << 6, tid);
    }

    atomicAdd(&srow[grow], rs0);
    atomicAdd(&srow[grow + 8], rs1);
    __syncthreads();
    if (tid < 64) srow[tid] = __fdividef(1.0f, srow[tid]);
    __syncthreads();

    const float s0 = srow[grow], s1 = srow[grow + 8];
#pragma unroll
    for (int t = 0; t < 8; t++) {
        const int lc = 8 * t + c2;
        const float b0 = sbias[lc], b1 = sbias[lc + 1];
        float* dst = out + (size_t)(n0 + grow) * 1024 + (g << 6) + lc;
        *(float2*)dst = make_float2(fmaf(acc2[t][0], s0, b0),
                                    fmaf(acc2[t][1], s0, b1));
        *(float2*)(dst + 1024 * 8) = make_float2(fmaf(acc2[t][2], s1, b0),
                                                 fmaf(acc2[t][3], s1, b1));
    }
}

// ---------------------------------------------------------------------------
extern "C" void kernel_launch(void* const* d_in, const int* in_sizes, int n_in,
                              void* d_out, int out_size)
{
    const float* roi = (const float*)d_in[0];
    const float* pe  = (const float*)d_in[1];
    int ix = 2;
    if (ix < n_in && in_sizes[ix] == 1) ix++;
    const float* pos_w = (const float*)d_in[ix++];
    const float* pos_b = (const float*)d_in[ix++];
    const float* q_w   = (const float*)d_in[ix++];
    const float* q_b   = (const float*)d_in[ix++];
    const float* k_w   = (const float*)d_in[ix++];
    const float* k_b   = (const float*)d_in[ix++];
    const float* out_w = (const float*)d_in[ix++];
    const float* out_b = (const float*)d_in[ix++];
    float* out = (float*)d_out;

    cudaFuncSetAttribute(k13, cudaFuncAttributeMaxDynamicSharedMemorySize,
                         K1_DSMEM);
    cudaFuncSetAttribute(k234, cudaFuncAttributeMaxDynamicSharedMemorySize,
                         K234_DSMEM);

    k0_convert<<<4096,         256>>>(roi, q_w, k_w, out_w);
    k13       <<<296,          256, K1_DSMEM>>>(q_b, k_b, pe, pos_w, pos_b);
    k234      <<<dim3(16, 16), 128, K234_DSMEM>>>(out, out_b);
}

// round 17
// speedup vs baseline: 1.1293x; 1.1293x over previous
#include <cuda_runtime.h>
#include <cuda_bf16.h>
#include <cuda_fp16.h>
#include <cstdint>

// ---------------------------------------------------------------------------
// RelationNetwork v17  (= v15 + k234 double-buffered P, fused commit group).
// k0  : fp32 -> bf16 hi/lo split of [roi; q_w; k_w; out_w]
// k13 : UBER-KERNEL (v15 form). blocks [0,192): K1 mma GEMM; blocks
//       [192,1216): K3a pos-proj stream -> pf fp16.
// k234: fused aff+softmax+output GEMM, register-direct; S+pf+P prefetched
//       together one iteration ahead (P 2-stage).
// ---------------------------------------------------------------------------

__device__ __half g_pfh[1024u * 16u * 1024u];            // 32 MB [n][g][m] fp16
__device__ __nv_bfloat16 g_hi [4096u * 1024u];           // input hi split
__device__ __nv_bfloat16 g_lo [4096u * 1024u];           // input lo split
__device__ __nv_bfloat16 g_qkh[2u * 16u * 1024u * 64u];  // Q,K hi [seg][g][n][64]
__device__ __nv_bfloat16 g_qkl[2u * 16u * 1024u * 64u];  // Q,K lo
__device__ __nv_bfloat16 g_ph [16u * 64u * 1024u];       // P^T hi [g][o][k]
__device__ __nv_bfloat16 g_pl [16u * 64u * 1024u];       // P^T lo

// ---- packed f32x2 helpers ---------------------------------------------------
__device__ __forceinline__ unsigned long long pack2(float a, float b) {
    unsigned long long r;
    asm("mov.b64 %0, {%1, %2};" : "=l"(r)
        : "r"(__float_as_uint(a)), "r"(__float_as_uint(b)));
    return r;
}
__device__ __forceinline__ void unpack2(unsigned long long v, float& a, float& b) {
    unsigned int lo, hi;
    asm("mov.b64 {%0, %1}, %2;" : "=r"(lo), "=r"(hi) : "l"(v));
    a = __uint_as_float(lo);
    b = __uint_as_float(hi);
}
__device__ __forceinline__ unsigned long long fma2(unsigned long long a,
                                                   unsigned long long b,
                                                   unsigned long long c) {
    unsigned long long d;
    asm("fma.rn.f32x2 %0, %1, %2, %3;" : "=l"(d) : "l"(a), "l"(b), "l"(c));
    return d;
}

// ---- mma.sync / cp.async helpers --------------------------------------------
__device__ __forceinline__ uint32_t smem_u32(const void* p) {
    uint32_t a;
    asm("{ .reg .u64 t; cvta.to.shared.u64 t, %1; cvt.u32.u64 %0, t; }"
        : "=r"(a) : "l"(p));
    return a;
}
#define CP16(s, g) \
    asm volatile("cp.async.cg.shared.global [%0], [%1], 16;" \
                 :: "r"(s), "l"(g) : "memory")
#define CP_COMMIT() asm volatile("cp.async.commit_group;" ::: "memory")
#define CP_WAIT(n)  asm volatile("cp.async.wait_group %0;" :: "n"(n) : "memory")
#define LDSM4(r, a) \
    asm volatile("ldmatrix.sync.aligned.m8n8.x4.shared.b16 {%0,%1,%2,%3}, [%4];" \
                 : "=r"((r)[0]), "=r"((r)[1]), "=r"((r)[2]), "=r"((r)[3]) \
                 : "r"(a))
#define MMA_BF16(d, a, b0, b1) \
    asm volatile("mma.sync.aligned.m16n8k16.row.col.f32.bf16.bf16.f32 " \
                 "{%0,%1,%2,%3}, {%4,%5,%6,%7}, {%8,%9}, {%0,%1,%2,%3};" \
                 : "+f"((d)[0]), "+f"((d)[1]), "+f"((d)[2]), "+f"((d)[3]) \
                 : "r"((a)[0]), "r"((a)[1]), "r"((a)[2]), "r"((a)[3]), \
                   "r"(b0), "r"(b1))

// pack two fp32 -> bf16x2 register (lo = a, hi = b)
__device__ __forceinline__ uint32_t bf2pack(float a, float b) {
    uint32_t r;
    asm("cvt.rn.bf16x2.f32 %0, %1, %2;" : "=r"(r) : "f"(b), "f"(a));
    return r;
}

// 64B-row swizzle: 4 chunks of 16B permuted by row pair.
__device__ __forceinline__ uint32_t swz(int r, int c) {
    return (uint32_t)(r * 64 + (((c ^ ((r >> 1) & 3)) & 3) << 4));
}
// 128B-row SW128 swizzle.
__device__ __forceinline__ uint32_t sw128(uint32_t off) {
    return off ^ ((off >> 3) & 0x70);
}

// ---------------------------------------------------------------------------
// k0: split [roi; q_w; k_w; out_w] into bf16 hi + lo.
// ---------------------------------------------------------------------------
__global__ __launch_bounds__(256) void k0_convert(
    const float* __restrict__ roi, const float* __restrict__ qw,
    const float* __restrict__ kw,  const float* __restrict__ ow)
{
    const size_t e = ((size_t)blockIdx.x * 256 + threadIdx.x) * 4;
    const float* src;
    size_t off;
    if (e < (1u << 20))      { src = roi; off = e; }
    else if (e < (2u << 20)) { src = qw;  off = e - (1u << 20); }
    else if (e < (3u << 20)) { src = kw;  off = e - (2u << 20); }
    else                     { src = ow;  off = e - (3u << 20); }
    const float4 v = *(const float4*)(src + off);
    float x[4] = {v.x, v.y, v.z, v.w};
    __nv_bfloat16 h[4], l[4];
#pragma unroll
    for (int i = 0; i < 4; i++) {
        h[i] = __float2bfloat16(x[i]);
        l[i] = __float2bfloat16(x[i] - __bfloat162float(h[i]));
    }
    ((__nv_bfloat162*)(g_hi + e))[0] = __nv_bfloat162(h[0], h[1]);
    ((__nv_bfloat162*)(g_hi + e))[1] = __nv_bfloat162(h[2], h[3]);
    ((__nv_bfloat162*)(g_lo + e))[0] = __nv_bfloat162(l[0], l[1]);
    ((__nv_bfloat162*)(g_lo + e))[1] = __nv_bfloat162(l[2], l[3]);
}

// ---------------------------------------------------------------------------
// K1 path pieces (used inside k13).
// ---------------------------------------------------------------------------
#define K1_STAGE 32768
#define K1_DSMEM 67584

__device__ __forceinline__ void k1_issue(uint32_t so, int row0, int col0,
                                         int kc, int tid)
{
#pragma unroll
    for (int j = 0; j < 2; j++) {
        const int id = tid + (j << 8);
        const int r = id >> 2, c = id & 3;
        const uint32_t s = so + swz(r, c);
        const size_t goA = (size_t)(row0 + r) * 1024 + (kc << 5) + (c << 3);
        const size_t goB = (size_t)(1024 + col0 + r) * 1024 + (kc << 5) + (c << 3);
        CP16(s,         g_hi + goA);
        CP16(s +  8192, g_lo + goA);
        CP16(s + 16384, g_hi + goB);
        CP16(s + 24576, g_lo + goB);
    }
    CP_COMMIT();
}

__device__ __forceinline__ void k1_compute(uint32_t so, float acc[4][4][4],
                                           int wm, int wn, int lane)
{
    const int arow = lane & 15;
    const int achk = lane >> 4;
#pragma unroll
    for (int ks = 0; ks < 2; ks++) {
        uint32_t ah[4][4], al[4][4], bh[2][4], bl[2][4];
#pragma unroll
        for (int mi = 0; mi < 4; mi++) {
            const int r = wm * 64 + mi * 16 + arow;
            const uint32_t addr = so + swz(r, ks * 2 + achk);
            LDSM4(ah[mi], addr);
            LDSM4(al[mi], addr + 8192);
        }
#pragma unroll
        for (int nj = 0; nj < 2; nj++) {
            const int r = wn * 32 + nj * 16 + arow;
            const uint32_t addr = so + 16384 + swz(r, ks * 2 + achk);
            LDSM4(bh[nj], addr);
            LDSM4(bl[nj], addr + 8192);
        }
#pragma unroll
        for (int mi = 0; mi < 4; mi++)
#pragma unroll
            for (int n = 0; n < 4; n++) {
                const int nj = n >> 1, sb = n & 1;
                MMA_BF16(acc[mi][n], ah[mi], bh[nj][sb], bh[nj][sb + 2]);
                MMA_BF16(acc[mi][n], ah[mi], bl[nj][sb], bl[nj][sb + 2]);
                MMA_BF16(acc[mi][n], al[mi], bh[nj][sb], bh[nj][sb + 2]);
            }
    }
}

// ---------------------------------------------------------------------------
// k13: uber-kernel (v15 form). blocks [0,192) = K1; blocks [192,1216) = K3a.
// ---------------------------------------------------------------------------
__global__ __launch_bounds__(256, 2) void k13(
    const float* __restrict__ qb, const float* __restrict__ kb,
    const float* __restrict__ pe, const float* __restrict__ pw,
    const float* __restrict__ pb)
{
    extern __shared__ char sm1[];
    const int tid = threadIdx.x;

    if (blockIdx.x < 192) {
        // =========================== K1 path ================================
        __shared__ float sbias[128];
        const uint32_t sbase = smem_u32(sm1);
        const int lane = tid & 31, wid = tid >> 5;
        const int wm = wid >> 2, wn = wid & 3;
        const int col0 = (blockIdx.x % 24) << 7;
        const int row0 = (blockIdx.x / 24) << 7;
        const int seg = col0 >> 10, jb0 = col0 & 1023;

        if (tid < 128)
            sbias[tid] = (seg == 0) ? qb[jb0 + tid]
                       : ((seg == 1) ? kb[jb0 + tid] : 0.0f);

        float acc[4][4][4];
#pragma unroll
        for (int i = 0; i < 4; i++)
#pragma unroll
            for (int j = 0; j < 4; j++)
#pragma unroll
                for (int q = 0; q < 4; q++) acc[i][j][q] = 0.0f;

        k1_issue(sbase, row0, col0, 0, tid);

#pragma unroll 1
        for (int kc = 0; kc < 32; kc++) {
            const uint32_t so = sbase + ((kc & 1) ? (uint32_t)K1_STAGE : 0u);
            if (kc < 31) {
                k1_issue(sbase + (((kc + 1) & 1) ? (uint32_t)K1_STAGE : 0u),
                         row0, col0, kc + 1, tid);
                CP_WAIT(1);
            } else {
                CP_WAIT(0);
            }
            __syncthreads();
            k1_compute(so, acc, wm, wn, lane);
            __syncthreads();
        }

        if (seg < 2) {
#pragma unroll
            for (int mi = 0; mi < 4; mi++) {
                const int r0 = row0 + wm * 64 + mi * 16 + (lane >> 2);
#pragma unroll
                for (int n = 0; n < 4; n++) {
                    const int lc = wn * 32 + n * 8 + ((lane & 3) << 1);
                    const int jl = jb0 + lc;
                    const int g = jl >> 6, d0 = jl & 63;
                    const float b0 = sbias[lc], b1 = sbias[lc + 1];
                    const float f00 = acc[mi][n][0] + b0;
                    const float f01 = acc[mi][n][1] + b1;
                    const float f10 = acc[mi][n][2] + b0;
                    const float f11 = acc[mi][n][3] + b1;
                    const size_t bi = ((size_t)(seg * 16 + g) * 1024) * 64 + d0;
                    __nv_bfloat16 h00 = __float2bfloat16(f00);
                    __nv_bfloat16 h01 = __float2bfloat16(f01);
                    __nv_bfloat16 h10 = __float2bfloat16(f10);
                    __nv_bfloat16 h11 = __float2bfloat16(f11);
                    *(__nv_bfloat162*)(g_qkh + bi + (size_t)r0 * 64) =
                        __nv_bfloat162(h00, h01);
                    *(__nv_bfloat162*)(g_qkh + bi + (size_t)(r0 + 8) * 64) =
                        __nv_bfloat162(h10, h11);
                    *(__nv_bfloat162*)(g_qkl + bi + (size_t)r0 * 64) =
                        __nv_bfloat162(
                            __float2bfloat16(f00 - __bfloat162float(h00)),
                            __float2bfloat16(f01 - __bfloat162float(h01)));
                    *(__nv_bfloat162*)(g_qkl + bi + (size_t)(r0 + 8) * 64) =
                        __nv_bfloat162(
                            __float2bfloat16(f10 - __bfloat162float(h10)),
                            __float2bfloat16(f11 - __bfloat162float(h11)));
                }
            }
        } else {
            // transpose through smem: smf[col][row] stride 132
            float* smf = (float*)sm1;
#pragma unroll
            for (int mi = 0; mi < 4; mi++) {
                const int rl = wm * 64 + mi * 16 + (lane >> 2);
#pragma unroll
                for (int n = 0; n < 4; n++) {
                    const int lc = wn * 32 + n * 8 + ((lane & 3) << 1);
                    smf[lc * 132 + rl]           = acc[mi][n][0];
                    smf[(lc + 1) * 132 + rl]     = acc[mi][n][1];
                    smf[lc * 132 + rl + 8]       = acc[mi][n][2];
                    smf[(lc + 1) * 132 + rl + 8] = acc[mi][n][3];
                }
            }
            __syncthreads();
            const int c = tid >> 1, half = tid & 1;
            const int jl = jb0 + c;
            const int g = jl >> 6, o = jl & 63;
            __nv_bfloat16* dh = g_ph + ((size_t)g * 64 + o) * 1024 +
                                row0 + half * 64;
            __nv_bfloat16* dl = g_pl + ((size_t)g * 64 + o) * 1024 +
                                row0 + half * 64;
            const float* srow = smf + c * 132 + half * 64;
#pragma unroll
            for (int i4 = 0; i4 < 16; i4++) {
                const float4 v = *(const float4*)(srow + i4 * 4);
                __nv_bfloat16 h0 = __float2bfloat16(v.x);
                __nv_bfloat16 h1 = __float2bfloat16(v.y);
                __nv_bfloat16 h2 = __float2bfloat16(v.z);
                __nv_bfloat16 h3 = __float2bfloat16(v.w);
                ((__nv_bfloat162*)(dh + i4 * 4))[0] = __nv_bfloat162(h0, h1);
                ((__nv_bfloat162*)(dh + i4 * 4))[1] = __nv_bfloat162(h2, h3);
                ((__nv_bfloat162*)(dl + i4 * 4))[0] = __nv_bfloat162(
                    __float2bfloat16(v.x - __bfloat162float(h0)),
                    __float2bfloat16(v.y - __bfloat162float(h1)));
                ((__nv_bfloat162*)(dl + i4 * 4))[1] = __nv_bfloat162(
                    __float2bfloat16(v.z - __bfloat162float(h2)),
                    __float2bfloat16(v.w - __bfloat162float(h3)));
            }
        }
    } else {
        // =========================== K3a path ===============================
        // pf[n][g][m] = max(pos_w@pe + pos_b, 1e-6)  -> fp16
        __shared__ ulonglong2 swd2[16][32];
        __shared__ float sb3[16];
        const int n = blockIdx.x - 192;

        for (int idx = tid; idx < 1024; idx += 256) {
            const float w = pw[idx];
            ((unsigned long long*)swd2)[idx] = pack2(w, w);
        }
        if (tid < 16) sb3[tid] = pb[tid];
        __syncthreads();

        const int m0 = tid << 2;
        unsigned long long acc[16][2];
#pragma unroll
        for (int gg = 0; gg < 16; gg++) { acc[gg][0] = 0ULL; acc[gg][1] = 0ULL; }

        const float* base = pe + (size_t)n * 1024 + m0;
        ulonglong2 cur[8];
#pragma unroll
        for (int j = 0; j < 8; j++)
            cur[j] = __ldg((const ulonglong2*)(base + (size_t)j * 1048576));

#pragma unroll 1
        for (int e0 = 0; e0 < 64; e0 += 8) {
            ulonglong2 nxt[8];
            const int eb = (e0 + 8) & 63;
#pragma unroll
            for (int j = 0; j < 8; j++)
                nxt[j] = __ldg((const ulonglong2*)
                               (base + (size_t)(eb + j) * 1048576));
#pragma unroll
            for (int j = 0; j < 8; j += 2) {
                const ulonglong2 c0 = cur[j], c1 = cur[j + 1];
                const int ep = (e0 + j) >> 1;
#pragma unroll
                for (int gg = 0; gg < 16; gg++) {
                    const ulonglong2 w = swd2[gg][ep];
                    acc[gg][0] = fma2(w.x, c0.x, acc[gg][0]);
                    acc[gg][0] = fma2(w.y, c1.x, acc[gg][0]);
                    acc[gg][1] = fma2(w.x, c0.y, acc[gg][1]);
                    acc[gg][1] = fma2(w.y, c1.y, acc[gg][1]);
                }
            }
#pragma unroll
            for (int j = 0; j < 8; j++) cur[j] = nxt[j];
        }

        __half* pfp = g_pfh + (size_t)n * 16 * 1024 + m0;
#pragma unroll
        for (int gg = 0; gg < 16; gg++) {
            float x0, x1, x2, x3;
            unpack2(acc[gg][0], x0, x1);
            unpack2(acc[gg][1], x2, x3);
            const float bgg = sb3[gg];
            __half2 ha = __floats2half2_rn(fmaxf(x0 + bgg, 1e-6f),
                                           fmaxf(x1 + bgg, 1e-6f));
            __half2 hb = __floats2half2_rn(fmaxf(x2 + bgg, 1e-6f),
                                           fmaxf(x3 + bgg, 1e-6f));
            uint2 v;
            v.x = *reinterpret_cast<uint32_t*>(&ha);
            v.y = *reinterpret_cast<uint32_t*>(&hb);
            *(uint2*)(pfp + (size_t)gg * 1024) = v;
        }
    }
}

// ---------------------------------------------------------------------------
// k234: fused aff + softmax + output GEMM, register-direct, pf fp16.
// Block = (g, 64n), 128 threads (4 warps x 16n x 64m / 64o).
// smem: Q hi/lo 16K @0 | 2 S-stages @16K (K 16K + pf 64x144B) | 2 P-stages 16K.
// S, pf and P for chunk kc+1 issue together in ONE commit group, a full
// iteration ahead -> P latency fully hidden.
// ---------------------------------------------------------------------------
#define K234_ST0   16384
#define K234_STAGE 25600
#define K234_LWOFF 16384
#define K234_POFF  (K234_ST0 + 2 * K234_STAGE)      // 67584
#define K234_DSMEM (K234_POFF + 2 * 16384)          // 100352

__device__ __forceinline__ void k234_issueSP(uint32_t so, uint32_t pp,
                                             int g, int n0, int m0, int tid)
{
    // K chunk: 64 m-rows x 64 d (128B rows), hi+lo
#pragma unroll
    for (int j = 0; j < 4; j++) {
        const int id = tid + (j << 7);
        const int r = id >> 3, c = id & 7;
        const size_t go = ((size_t)((16 + g) * 1024) + m0 + r) * 64 + (c << 3);
        const uint32_t s = so + sw128((r << 7) + (c << 4));
        CP16(s,        g_qkh + go);
        CP16(s + 8192, g_qkl + go);
    }
    // pf chunk: 64 n-rows x 64 m fp16, stride 144B
#pragma unroll
    for (int j = 0; j < 4; j++) {
        const int id = tid + (j << 7);
        const int r = id >> 3, c = id & 7;
        CP16(so + K234_LWOFF + r * 144 + (c << 4),
             g_pfh + ((size_t)(n0 + r) * 16 + g) * 1024 + m0 + (c << 3));
    }
    // P chunk: 64 o-rows x 64 k (128B rows), hi+lo
#pragma unroll
    for (int j = 0; j < 4; j++) {
        const int id = tid + (j << 7);
        const int r = id >> 3, c = id & 7;
        const size_t gb = ((size_t)g * 64 + r) * 1024 + m0 + (c << 3);
        const uint32_t s = pp + sw128((r << 7) + (c << 4));
        CP16(s,        g_ph + gb);
        CP16(s + 8192, g_pl + gb);
    }
    CP_COMMIT();
}

__global__ __launch_bounds__(128, 2) void k234(float* __restrict__ out,
                                               const float* __restrict__ obias)
{
    extern __shared__ char smx[];
    __shared__ float srow[64];
    __shared__ float sbias[64];
    const uint32_t sbase = smem_u32(smx);
    const int tid = threadIdx.x, lane = tid & 31, w = tid >> 5;   // 4 warps
    const int n0 = blockIdx.x << 6, g = blockIdx.y;

    if (tid < 64) {
        srow[tid] = 0.0f;
        sbias[tid] = obias[(g << 6) + tid];
    }

    // Q prologue (joins the S0+P0 commit group)
#pragma unroll
    for (int j = 0; j < 4; j++) {
        const int id = tid + (j << 7);
        const int r = id >> 3, c = id & 7;
        const size_t go = ((size_t)(g * 1024) + n0 + r) * 64 + (c << 3);
        const uint32_t s = sbase + sw128((r << 7) + (c << 4));
        CP16(s,        g_qkh + go);
        CP16(s + 8192, g_qkl + go);
    }
    k234_issueSP(sbase + K234_ST0, sbase + K234_POFF, g, n0, 0, tid);

    const int arow = lane & 15, achk = lane >> 4;
    const int r = lane >> 2, c2 = (lane & 3) << 1;
    const int grow = w * 16 + r;

    float acc2[8][4];
#pragma unroll
    for (int t = 0; t < 8; t++)
#pragma unroll
        for (int q = 0; q < 4; q++) acc2[t][q] = 0.0f;
    float rs0 = 0.0f, rs1 = 0.0f;

#pragma unroll 1
    for (int kc = 0; kc < 16; kc++) {
        const uint32_t so = sbase + K234_ST0 + (kc & 1) * (uint32_t)K234_STAGE;
        const uint32_t pa = sbase + K234_POFF + (kc & 1) * 16384u;
        const char* lwb = smx + (so - sbase) + K234_LWOFF;
        if (kc < 15) {
            k234_issueSP(sbase + K234_ST0 + ((kc + 1) & 1) * (uint32_t)K234_STAGE,
                         sbase + K234_POFF + ((kc + 1) & 1) * 16384u,
                         g, n0, (kc + 1) << 6, tid);
            CP_WAIT(1);
        } else {
            CP_WAIT(0);
        }
        __syncthreads();

        // ---- MMA1: aff chunk ----
        float acc1[8][4];
#pragma unroll
        for (int t = 0; t < 8; t++)
#pragma unroll
            for (int q = 0; q < 4; q++) acc1[t][q] = 0.0f;

#pragma unroll
        for (int ks = 0; ks < 4; ks++) {
            uint32_t ah4[4], al4[4];
            {
                const uint32_t addr = sbase +
                    sw128(((w * 16 + arow) << 7) + (ks << 5) + (achk << 4));
                LDSM4(ah4, addr);
                LDSM4(al4, addr + 8192);
            }
#pragma unroll
            for (int t = 0; t < 4; t++) {
                uint32_t bh[4], bl[4];
                const uint32_t addr = so +
                    sw128(((t * 16 + arow) << 7) + (ks << 5) + (achk << 4));
                LDSM4(bh, addr);
                LDSM4(bl, addr + 8192);
#pragma unroll
                for (int s = 0; s < 2; s++) {
                    const int nj = 2 * t + s;
                    MMA_BF16(acc1[nj], ah4, bh[s], bh[s + 2]);
                    MMA_BF16(acc1[nj], ah4, bl[s], bl[s + 2]);
                    MMA_BF16(acc1[nj], al4, bh[s], bh[s + 2]);
                }
            }
        }

        // ---- exp in registers ----
#pragma unroll
        for (int t = 0; t < 8; t++) {
            const int mc = 8 * t + c2;
            const __half2 p0 =
                *(const __half2*)(lwb + grow * 144 + (mc << 1));
            const __half2 p1 =
                *(const __half2*)(lwb + (grow + 8) * 144 + (mc << 1));
            const float2 f0 = __half22float2(p0);
            const float2 f1 = __half22float2(p1);
            const float e0 = f0.x * __expf(0.125f * acc1[t][0]);
            const float e1 = f0.y * __expf(0.125f * acc1[t][1]);
            const float e2 = f1.x * __expf(0.125f * acc1[t][2]);
            const float e3 = f1.y * __expf(0.125f * acc1[t][3]);
            rs0 += e0 + e1;
            rs1 += e2 + e3;
            acc1[t][0] = e0; acc1[t][1] = e1;
            acc1[t][2] = e2; acc1[t][3] = e3;
        }

        // ---- MMA2 A-fragments from C frags ----
        uint32_t eh[4][4], el[4][4];
#pragma unroll
        for (int j = 0; j < 4; j++) {
#pragma unroll
            for (int h = 0; h < 4; h++) {
                const int t = 2 * j + (h >> 1);
                const float x = acc1[t][(h & 1) * 2];
                const float y = acc1[t][(h & 1) * 2 + 1];
                const uint32_t hp = bf2pack(x, y);
                eh[j][h] = hp;
                const __nv_bfloat162 hv = *(const __nv_bfloat162*)&hp;
                el[j][h] = bf2pack(x - __bfloat162float(hv.x),
                                   y - __bfloat162float(hv.y));
            }
        }

        // ---- MMA2: out += exp @ P^T ----
#pragma unroll
        for (int ks = 0; ks < 4; ks++) {
#pragma unroll
            for (int t = 0; t < 4; t++) {
                uint32_t bh[4], bl[4];
                const uint32_t addr = pa +
                    sw128(((t * 16 + arow) << 7) + (ks << 5) + (achk << 4));
                LDSM4(bh, addr);
                LDSM4(bl, addr + 8192);
#pragma unroll
                for (int s = 0; s < 2; s++) {
                    const int nj = 2 * t + s;
                    MMA_BF16(acc2[nj], eh[ks], bh[s], bh[s + 2]);
                    MMA_BF16(acc2[nj], eh[ks], bl[s], bl[s + 2]);
                    MMA_BF16(acc2[nj], el[ks], bh[s], bh[s + 2]);
                }
            }
        }
        __syncthreads();   // stage kc reads complete before kc+2 overwrite
    }

    atomicAdd(&srow[grow], rs0);
    atomicAdd(&srow[grow + 8], rs1);
    __syncthreads();
    if (tid < 64) srow[tid] = __fdividef(1.0f, srow[tid]);
    __syncthreads();

    const float s0 = srow[grow], s1 = srow[grow + 8];
#pragma unroll
    for (int t = 0; t < 8; t++) {
        const int lc = 8 * t + c2;
        const float b0 = sbias[lc], b1 = sbias[lc + 1];
        float* dst = out + (size_t)(n0 + grow) * 1024 + (g << 6) + lc;
        *(float2*)dst = make_float2(fmaf(acc2[t][0], s0, b0),
                                    fmaf(acc2[t][1], s0, b1));
        *(float2*)(dst + 1024 * 8) = make_float2(fmaf(acc2[t][2], s1, b0),
                                                 fmaf(acc2[t][3], s1, b1));
    }
}

// ---------------------------------------------------------------------------
extern "C" void kernel_launch(void* const* d_in, const int* in_sizes, int n_in,
                              void* d_out, int out_size)
{
    const float* roi = (const float*)d_in[0];
    const float* pe  = (const float*)d_in[1];
    int ix = 2;
    if (ix < n_in && in_sizes[ix] == 1) ix++;
    const float* pos_w = (const float*)d_in[ix++];
    const float* pos_b = (const float*)d_in[ix++];
    const float* q_w   = (const float*)d_in[ix++];
    const float* q_b   = (const float*)d_in[ix++];
    const float* k_w   = (const float*)d_in[ix++];
    const float* k_b   = (const float*)d_in[ix++];
    const float* out_w = (const float*)d_in[ix++];
    const float* out_b = (const float*)d_in[ix++];
    float* out = (float*)d_out;

    cudaFuncSetAttribute(k13, cudaFuncAttributeMaxDynamicSharedMemorySize,
                         K1_DSMEM);
    cudaFuncSetAttribute(k234, cudaFuncAttributeMaxDynamicSharedMemorySize,
                         K234_DSMEM);

    k0_convert<<<4096,         256>>>(roi, q_w, k_w, out_w);
    k13       <<<1216,         256, K1_DSMEM>>>(q_b, k_b, pe, pos_w, pos_b);
    k234      <<<dim3(16, 16), 128, K234_DSMEM>>>(out, out_b);
}